// round 1
// baseline (speedup 1.0000x reference)
#include <cuda_runtime.h>
#include <cuda_bf16.h>
#include <math.h>

// ---------------------------------------------------------------------------
// DialogueTransformer: B=8, S=2048, D=1024, H=8, HD=128
// 14 GEMMs of [16384,1024] x [1024,1024]^T + 3 tiny per-position 8x8 head-mix
// attentions + PE add. All fp32 this round (correctness baseline).
// ---------------------------------------------------------------------------

#define MDIM 16384      // B*S
#define DDIM 1024
#define HDIM 8
#define HDHD 128

// 6 scratch activation buffers, 64 MB each (no cudaMalloc allowed).
__device__ float g_bufs[6][MDIM * DDIM];

// ---------------------------------------------------------------------------
// PE add: out[b,s,d] = in[b,s,d] + pe[d]
// ---------------------------------------------------------------------------
__global__ void add_pe_kernel(const float* __restrict__ in,
                              const float* __restrict__ pe,
                              float* __restrict__ out) {
    int idx = blockIdx.x * blockDim.x + threadIdx.x;   // float4 index
    float4 v = ((const float4*)in)[idx];
    int d = (idx & 255) * 4;                            // 256 float4 per row
    v.x += pe[d + 0];
    v.y += pe[d + 1];
    v.z += pe[d + 2];
    v.w += pe[d + 3];
    ((float4*)out)[idx] = v;
}

// ---------------------------------------------------------------------------
// GEMM: C[m,n] = sum_k A[m,k] * W[n,k] + bias[n]   (optionally ReLU)
// A: [16384,1024] row-major, W: [1024,1024] row-major (K contiguous in both).
// 128x128 block tile, BK=16, 256 threads, 8x8 per-thread micro-tile,
// double-buffered smem, one __syncthreads per K-iter.
// ---------------------------------------------------------------------------
#define BM 128
#define BN 128
#define BK 16

template <bool RELU>
__global__ __launch_bounds__(256, 2)
void gemm_kernel(const float* __restrict__ A,
                 const float* __restrict__ W,
                 const float* __restrict__ bias,
                 float* __restrict__ C) {
    __shared__ float As[2][BK][BM + 4];
    __shared__ float Ws[2][BK][BN + 4];

    const int tid = threadIdx.x;
    const int bm = blockIdx.y * BM;
    const int bn = blockIdx.x * BN;

    // loaders: each thread brings 2 float4 of A and 2 float4 of W per tile
    const int lr = tid >> 2;           // 0..63
    const int lc = (tid & 3) << 2;     // 0,4,8,12
    // compute fragment position
    const int tx = tid & 15;           // n
    const int ty = tid >> 4;           // m

    const float* Aptr = A + (size_t)(bm + lr) * DDIM + lc;
    const float* Wptr = W + (size_t)(bn + lr) * DDIM + lc;

    float4 ra0, ra1, rw0, rw1;

    // prologue: tile 0
    ra0 = *(const float4*)(Aptr);
    ra1 = *(const float4*)(Aptr + 64 * DDIM);
    rw0 = *(const float4*)(Wptr);
    rw1 = *(const float4*)(Wptr + 64 * DDIM);
#pragma unroll
    for (int i = 0; i < 4; i++) {
        As[0][lc + i][lr]      = ((const float*)&ra0)[i];
        As[0][lc + i][lr + 64] = ((const float*)&ra1)[i];
        Ws[0][lc + i][lr]      = ((const float*)&rw0)[i];
        Ws[0][lc + i][lr + 64] = ((const float*)&rw1)[i];
    }
    __syncthreads();

    float acc[8][8];
#pragma unroll
    for (int i = 0; i < 8; i++)
#pragma unroll
        for (int j = 0; j < 8; j++) acc[i][j] = 0.0f;

    const int NKB = DDIM / BK;   // 64
    for (int kb = 0; kb < NKB; ++kb) {
        const int cur = kb & 1;
        if (kb + 1 < NKB) {
            const float* Ap = Aptr + (kb + 1) * BK;
            const float* Wp = Wptr + (kb + 1) * BK;
            ra0 = *(const float4*)(Ap);
            ra1 = *(const float4*)(Ap + 64 * DDIM);
            rw0 = *(const float4*)(Wp);
            rw1 = *(const float4*)(Wp + 64 * DDIM);
        }
#pragma unroll
        for (int kt = 0; kt < BK; ++kt) {
            float a[8], b[8];
            *(float4*)&a[0] = *(const float4*)&As[cur][kt][ty * 4];
            *(float4*)&a[4] = *(const float4*)&As[cur][kt][64 + ty * 4];
            *(float4*)&b[0] = *(const float4*)&Ws[cur][kt][tx * 4];
            *(float4*)&b[4] = *(const float4*)&Ws[cur][kt][64 + tx * 4];
#pragma unroll
            for (int i = 0; i < 8; i++)
#pragma unroll
                for (int j = 0; j < 8; j++) acc[i][j] += a[i] * b[j];
        }
        if (kb + 1 < NKB) {
            const int nxt = cur ^ 1;
#pragma unroll
            for (int i = 0; i < 4; i++) {
                As[nxt][lc + i][lr]      = ((const float*)&ra0)[i];
                As[nxt][lc + i][lr + 64] = ((const float*)&ra1)[i];
                Ws[nxt][lc + i][lr]      = ((const float*)&rw0)[i];
                Ws[nxt][lc + i][lr + 64] = ((const float*)&rw1)[i];
            }
        }
        __syncthreads();
    }

    // epilogue: bias (+ReLU), vectorized stores
#pragma unroll
    for (int i = 0; i < 8; i++) {
        const int m = bm + ((i < 4) ? (ty * 4 + i) : (64 + ty * 4 + i - 4));
        float* Crow = C + (size_t)m * DDIM + bn;
#pragma unroll
        for (int jj = 0; jj < 2; jj++) {
            const int n0 = (jj == 0) ? (tx * 4) : (64 + tx * 4);
            float4 o;
            o.x = acc[i][jj * 4 + 0] + bias[bn + n0 + 0];
            o.y = acc[i][jj * 4 + 1] + bias[bn + n0 + 1];
            o.z = acc[i][jj * 4 + 2] + bias[bn + n0 + 2];
            o.w = acc[i][jj * 4 + 3] + bias[bn + n0 + 3];
            if (RELU) {
                o.x = fmaxf(o.x, 0.0f);
                o.y = fmaxf(o.y, 0.0f);
                o.z = fmaxf(o.z, 0.0f);
                o.w = fmaxf(o.w, 0.0f);
            }
            *(float4*)(Crow + n0) = o;
        }
    }
}

// ---------------------------------------------------------------------------
// Per-position head-mix attention. One block (128 threads) per (b,s):
// q,k,v are [8,128] slices of the same row. scores[i,j]=q_i.k_j/sqrt(128),
// softmax over j, out_i = sum_j w_ij v_j.
// ---------------------------------------------------------------------------
__global__ void attn_kernel(const float* __restrict__ Q,
                            const float* __restrict__ K,
                            const float* __restrict__ V,
                            float* __restrict__ O) {
    __shared__ float sq[1024];
    __shared__ float sk[1024];
    __shared__ float sw[64];

    const int p = blockIdx.x;
    const int t = threadIdx.x;    // 0..127
    const size_t base = (size_t)p * 1024;

    // load q, k (256 float4 each; 2 per thread)
    ((float4*)sq)[t]       = ((const float4*)(Q + base))[t];
    ((float4*)sq)[t + 128] = ((const float4*)(Q + base))[t + 128];
    ((float4*)sk)[t]       = ((const float4*)(K + base))[t];
    ((float4*)sk)[t + 128] = ((const float4*)(K + base))[t + 128];
    __syncthreads();

    // scores
    if (t < 64) {
        const int i = t >> 3, j = t & 7;
        const float* qi = &sq[i * 128];
        const float* kj = &sk[j * 128];
        float s = 0.0f;
#pragma unroll 8
        for (int h = 0; h < 128; h++) s += qi[h] * kj[h];
        sw[t] = s * 0.08838834764831845f;   // 1/sqrt(128)
    }
    __syncthreads();

    // softmax over j (one thread per row i)
    if (t < 8) {
        float m = sw[t * 8];
#pragma unroll
        for (int j = 1; j < 8; j++) m = fmaxf(m, sw[t * 8 + j]);
        float s = 0.0f;
        float e[8];
#pragma unroll
        for (int j = 0; j < 8; j++) { e[j] = __expf(sw[t * 8 + j] - m); s += e[j]; }
        const float inv = 1.0f / s;
#pragma unroll
        for (int j = 0; j < 8; j++) sw[t * 8 + j] = e[j] * inv;
    }
    __syncthreads();

    // out[i,h] = sum_j w[i,j] * v[j,h]; thread t = h
    float vj[8];
#pragma unroll
    for (int j = 0; j < 8; j++) vj[j] = V[base + j * 128 + t];
#pragma unroll
    for (int i = 0; i < 8; i++) {
        float acc = 0.0f;
#pragma unroll
        for (int j = 0; j < 8; j++) acc += sw[i * 8 + j] * vj[j];
        O[base + i * 128 + t] = acc;
    }
}

// ---------------------------------------------------------------------------
// Launch
// ---------------------------------------------------------------------------
extern "C" void kernel_launch(void* const* d_in, const int* in_sizes, int n_in,
                              void* d_out, int out_size) {
    const float* input_seq  = (const float*)d_in[0];
    const float* output_seq = (const float*)d_in[1];
    const float* pe         = (const float*)d_in[2];
    const float* enc_wq = (const float*)d_in[3];
    const float* enc_bq = (const float*)d_in[4];
    const float* enc_wk = (const float*)d_in[5];
    const float* enc_bk = (const float*)d_in[6];
    const float* enc_wv = (const float*)d_in[7];
    const float* enc_bv = (const float*)d_in[8];
    const float* enc_w1 = (const float*)d_in[9];
    const float* enc_b1 = (const float*)d_in[10];
    const float* enc_w2 = (const float*)d_in[11];
    const float* enc_b2 = (const float*)d_in[12];
    const float* dec_s_wq = (const float*)d_in[13];
    const float* dec_s_bq = (const float*)d_in[14];
    const float* dec_s_wk = (const float*)d_in[15];
    const float* dec_s_bk = (const float*)d_in[16];
    const float* dec_s_wv = (const float*)d_in[17];
    const float* dec_s_bv = (const float*)d_in[18];
    const float* dec_c_wq = (const float*)d_in[19];
    const float* dec_c_bq = (const float*)d_in[20];
    const float* dec_c_wk = (const float*)d_in[21];
    const float* dec_c_bk = (const float*)d_in[22];
    const float* dec_c_wv = (const float*)d_in[23];
    const float* dec_c_bv = (const float*)d_in[24];
    const float* dec_w1 = (const float*)d_in[25];
    const float* dec_b1 = (const float*)d_in[26];
    const float* dec_w2 = (const float*)d_in[27];
    const float* dec_b2 = (const float*)d_in[28];
    const float* fc_w   = (const float*)d_in[29];
    const float* fc_b   = (const float*)d_in[30];

    float* base = nullptr;
    cudaGetSymbolAddress((void**)&base, g_bufs);
    float* T0 = base + 0ull * MDIM * DDIM;
    float* T1 = base + 1ull * MDIM * DDIM;
    float* T2 = base + 2ull * MDIM * DDIM;
    float* T3 = base + 3ull * MDIM * DDIM;
    float* T4 = base + 4ull * MDIM * DDIM;
    float* T5 = base + 5ull * MDIM * DDIM;
    float* OUT = (float*)d_out;

    const dim3 ggrid(DDIM / BN, MDIM / BM);   // (8, 128)
    const int gthr = 256;

    // x = input + pe
    add_pe_kernel<<<MDIM * DDIM / 4 / 256, 256>>>(input_seq, pe, T0);

    // ---- encoder ----
    gemm_kernel<false><<<ggrid, gthr>>>(T0, enc_wq, enc_bq, T1);
    gemm_kernel<false><<<ggrid, gthr>>>(T0, enc_wk, enc_bk, T2);
    gemm_kernel<false><<<ggrid, gthr>>>(T0, enc_wv, enc_bv, T3);
    attn_kernel<<<MDIM, 128>>>(T1, T2, T3, T4);
    gemm_kernel<true ><<<ggrid, gthr>>>(T4, enc_w1, enc_b1, T5);
    gemm_kernel<false><<<ggrid, gthr>>>(T5, enc_w2, enc_b2, T0);   // enc_out -> T0

    // ---- decoder self-attn ----
    gemm_kernel<false><<<ggrid, gthr>>>(output_seq, dec_s_wq, dec_s_bq, T1);
    gemm_kernel<false><<<ggrid, gthr>>>(output_seq, dec_s_wk, dec_s_bk, T2);
    gemm_kernel<false><<<ggrid, gthr>>>(output_seq, dec_s_wv, dec_s_bv, T3);
    attn_kernel<<<MDIM, 128>>>(T1, T2, T3, T4);                    // sa -> T4

    // ---- decoder cross-attn (q from sa, k/v from enc_out) ----
    gemm_kernel<false><<<ggrid, gthr>>>(T4, dec_c_wq, dec_c_bq, T1);
    gemm_kernel<false><<<ggrid, gthr>>>(T0, dec_c_wk, dec_c_bk, T2);
    gemm_kernel<false><<<ggrid, gthr>>>(T0, dec_c_wv, dec_c_bv, T3);
    attn_kernel<<<MDIM, 128>>>(T1, T2, T3, T5);                    // ca -> T5

    // ---- decoder FFN + fc ----
    gemm_kernel<true ><<<ggrid, gthr>>>(T5, dec_w1, dec_b1, T1);
    gemm_kernel<false><<<ggrid, gthr>>>(T1, dec_w2, dec_b2, T2);
    gemm_kernel<false><<<ggrid, gthr>>>(T2, fc_w, fc_b, OUT);
}

// round 3
// speedup vs baseline: 1.6097x; 1.6097x over previous
#include <cuda_runtime.h>
#include <cuda_bf16.h>
#include <cstdint>

// ---------------------------------------------------------------------------
// DialogueTransformer on GB300 (sm_103a via base sm_103 PTX target):
// 14 GEMMs [16384,1024]x[1024,1024]^T as bf16x3 split-precision mma.sync
// (HMMA) with fp32 register accumulators + cp.async double buffering.
// tcgen05 is rejected by this harness's PTX target, so HMMA is the fastest
// available tensor path.
// ---------------------------------------------------------------------------

#define MDIM 16384
#define DDIM 1024

__device__ __align__(256) float g_bufs[6][MDIM * DDIM];
__device__ __align__(256) __nv_bfloat16 g_ahi[MDIM * DDIM];
__device__ __align__(256) __nv_bfloat16 g_alo[MDIM * DDIM];
__device__ __align__(256) __nv_bfloat16 g_whi[DDIM * DDIM];
__device__ __align__(256) __nv_bfloat16 g_wlo[DDIM * DDIM];

// ---------------------------------------------------------------------------
// PTX helpers (all baseline sm_80+ PTX; no arch-variant instructions)
// ---------------------------------------------------------------------------
__device__ __forceinline__ uint32_t smem_to_u32(const void* p) {
    uint32_t a;
    asm("{ .reg .u64 t; cvta.to.shared.u64 t, %1; cvt.u32.u64 %0, t; }" : "=r"(a) : "l"(p));
    return a;
}
__device__ __forceinline__ void cp_async16(uint32_t saddr, const void* gptr) {
    asm volatile("cp.async.cg.shared.global [%0], [%1], 16;" :: "r"(saddr), "l"(gptr));
}
__device__ __forceinline__ void cp_commit() { asm volatile("cp.async.commit_group;"); }
__device__ __forceinline__ void cp_wait_all() { asm volatile("cp.async.wait_group 0;" ::: "memory"); }

__device__ __forceinline__ void ldsm_x4(uint32_t* r, uint32_t addr) {
    asm volatile("ldmatrix.sync.aligned.m8n8.x4.shared.b16 {%0,%1,%2,%3}, [%4];"
                 : "=r"(r[0]), "=r"(r[1]), "=r"(r[2]), "=r"(r[3]) : "r"(addr));
}
__device__ __forceinline__ void mma16816(float* c, const uint32_t* a,
                                         uint32_t b0, uint32_t b1) {
    asm volatile(
        "mma.sync.aligned.m16n8k16.row.col.f32.bf16.bf16.f32 "
        "{%0,%1,%2,%3}, {%4,%5,%6,%7}, {%8,%9}, {%0,%1,%2,%3};"
        : "+f"(c[0]), "+f"(c[1]), "+f"(c[2]), "+f"(c[3])
        : "r"(a[0]), "r"(a[1]), "r"(a[2]), "r"(a[3]), "r"(b0), "r"(b1));
}

// ---------------------------------------------------------------------------
// bf16x3 GEMM: C[m,n] = sum_k A[m,k]*W[n,k] + bias[n]  (A,W pre-split hi/lo)
// BM=128, BN=128, BK=32, 256 threads (8 warps, 2x4 -> 64x32 warp tiles).
// Smem rows padded to 80B for conflict-free ldmatrix.
// ---------------------------------------------------------------------------
#define BM 128
#define BN 128
#define BK 32
#define NKB (DDIM / BK)   // 32
#define ROWB 80           // 32 bf16 = 64B payload + 16B pad
#define TILE_BYTES (128 * ROWB)            // 10240 per matrix
#define STAGE_BYTES (4 * TILE_BYTES)       // Ah, Al, Bh, Bl = 40960
#define GEMM_SMEM (2 * STAGE_BYTES)        // 81920

template <bool RELU>
__global__ __launch_bounds__(256)
void gemm_bf16x3(const __nv_bfloat16* __restrict__ Ahi,
                 const __nv_bfloat16* __restrict__ Alo,
                 const __nv_bfloat16* __restrict__ Whi,
                 const __nv_bfloat16* __restrict__ Wlo,
                 const float* __restrict__ bias,
                 float* __restrict__ C) {
    extern __shared__ char smem[];
    const uint32_t sb = smem_to_u32(smem);
    const int tid = threadIdx.x;
    const int wid = tid >> 5;
    const int lane = tid & 31;
    const int bm = blockIdx.y * BM;
    const int bn = blockIdx.x * BN;
    const int wm = (wid & 1) * 64;     // warp M offset in tile
    const int wn = (wid >> 1) * 32;    // warp N offset in tile

    // stage base offsets (bytes within smem)
    auto OFF_AH = [](int s) { return s * STAGE_BYTES + 0 * TILE_BYTES; };
    auto OFF_AL = [](int s) { return s * STAGE_BYTES + 1 * TILE_BYTES; };
    auto OFF_BH = [](int s) { return s * STAGE_BYTES + 2 * TILE_BYTES; };
    auto OFF_BL = [](int s) { return s * STAGE_BYTES + 3 * TILE_BYTES; };

    // ---- async stage fill: each thread copies 2 chunks x 4 matrices ----
    const int fr = tid >> 1;            // row 0..127
    const int fc0 = (tid & 1) * 2;      // chunk 0..3 (16B each)
    const __nv_bfloat16* gAh = Ahi + (size_t)(bm + fr) * DDIM;
    const __nv_bfloat16* gAl = Alo + (size_t)(bm + fr) * DDIM;
    const __nv_bfloat16* gBh = Whi + (size_t)(bn + fr) * DDIM;
    const __nv_bfloat16* gBl = Wlo + (size_t)(bn + fr) * DDIM;

    auto fill_stage = [&](int s, int kb) {
        const int k0 = kb * BK;
        const uint32_t srow = fr * ROWB;
#pragma unroll
        for (int i = 0; i < 2; i++) {
            const int c = fc0 + i;
            const uint32_t so = srow + c * 16;
            const int go = k0 + c * 8;
            cp_async16(sb + OFF_AH(s) + so, gAh + go);
            cp_async16(sb + OFF_AL(s) + so, gAl + go);
            cp_async16(sb + OFF_BH(s) + so, gBh + go);
            cp_async16(sb + OFF_BL(s) + so, gBl + go);
        }
        cp_commit();
    };

    fill_stage(0, 0);
    cp_wait_all();
    __syncthreads();

    float acc[4][4][4];
#pragma unroll
    for (int i = 0; i < 4; i++)
#pragma unroll
        for (int j = 0; j < 4; j++)
#pragma unroll
            for (int q = 0; q < 4; q++) acc[i][j][q] = 0.0f;

    // per-lane ldmatrix address components
    const uint32_t lrow = (lane & 15);
    const uint32_t lcol = (lane >> 4) * 16;

    for (int kb = 0; kb < NKB; kb++) {
        const int s = kb & 1;
        if (kb + 1 < NKB) fill_stage(s ^ 1, kb + 1);

        const uint32_t aHb = sb + OFF_AH(s) + (wm + lrow) * ROWB + lcol;
        const uint32_t aLb = sb + OFF_AL(s) + (wm + lrow) * ROWB + lcol;
        const uint32_t bHb = sb + OFF_BH(s) + (wn + lrow) * ROWB + lcol;
        const uint32_t bLb = sb + OFF_BL(s) + (wn + lrow) * ROWB + lcol;

#pragma unroll
        for (int ks = 0; ks < 2; ks++) {
            const uint32_t ko = ks * 32;   // 16 bf16 = 32 bytes
            uint32_t ah[4][4], al[4][4], bh[2][4], bl[2][4];
#pragma unroll
            for (int mt = 0; mt < 4; mt++) {
                ldsm_x4(ah[mt], aHb + mt * (16 * ROWB) + ko);
                ldsm_x4(al[mt], aLb + mt * (16 * ROWB) + ko);
            }
#pragma unroll
            for (int p = 0; p < 2; p++) {
                ldsm_x4(bh[p], bHb + p * (16 * ROWB) + ko);
                ldsm_x4(bl[p], bLb + p * (16 * ROWB) + ko);
            }
#pragma unroll
            for (int mt = 0; mt < 4; mt++) {
#pragma unroll
                for (int nt = 0; nt < 4; nt++) {
                    const int p = nt >> 1, o = nt & 1;
                    mma16816(acc[mt][nt], ah[mt], bh[p][o], bh[p][o + 2]);
                    mma16816(acc[mt][nt], ah[mt], bl[p][o], bl[p][o + 2]);
                    mma16816(acc[mt][nt], al[mt], bh[p][o], bh[p][o + 2]);
                }
            }
        }
        if (kb + 1 < NKB) cp_wait_all();
        __syncthreads();
    }

    // ---- epilogue: bias (+ReLU), float2 stores ----
    const int g = lane >> 2, t4 = lane & 3;
#pragma unroll
    for (int mt = 0; mt < 4; mt++) {
        const int row0 = bm + wm + mt * 16 + g;
        float* p0 = C + (size_t)row0 * DDIM + bn + wn;
        float* p1 = p0 + 8 * DDIM;
#pragma unroll
        for (int nt = 0; nt < 4; nt++) {
            const int col = nt * 8 + 2 * t4;
            const float bx = bias[bn + wn + col];
            const float by = bias[bn + wn + col + 1];
            float2 v0, v1;
            v0.x = acc[mt][nt][0] + bx;
            v0.y = acc[mt][nt][1] + by;
            v1.x = acc[mt][nt][2] + bx;
            v1.y = acc[mt][nt][3] + by;
            if (RELU) {
                v0.x = fmaxf(v0.x, 0.0f); v0.y = fmaxf(v0.y, 0.0f);
                v1.x = fmaxf(v1.x, 0.0f); v1.y = fmaxf(v1.y, 0.0f);
            }
            *(float2*)(p0 + col) = v0;
            *(float2*)(p1 + col) = v1;
        }
    }
}

// ---------------------------------------------------------------------------
// fp32 -> (bf16 hi, bf16 lo) split converters
// ---------------------------------------------------------------------------
__device__ __forceinline__ void split4(float4 v, __nv_bfloat162* H, __nv_bfloat162* L) {
    __nv_bfloat16 h0 = __float2bfloat16_rn(v.x);
    __nv_bfloat16 h1 = __float2bfloat16_rn(v.y);
    __nv_bfloat16 h2 = __float2bfloat16_rn(v.z);
    __nv_bfloat16 h3 = __float2bfloat16_rn(v.w);
    __nv_bfloat16 l0 = __float2bfloat16_rn(v.x - __bfloat162float(h0));
    __nv_bfloat16 l1 = __float2bfloat16_rn(v.y - __bfloat162float(h1));
    __nv_bfloat16 l2 = __float2bfloat16_rn(v.z - __bfloat162float(h2));
    __nv_bfloat16 l3 = __float2bfloat16_rn(v.w - __bfloat162float(h3));
    H[0] = __nv_bfloat162(h0, h1);
    H[1] = __nv_bfloat162(h2, h3);
    L[0] = __nv_bfloat162(l0, l1);
    L[1] = __nv_bfloat162(l2, l3);
}

__global__ void convert_split(const float* __restrict__ x,
                              __nv_bfloat16* __restrict__ hi,
                              __nv_bfloat16* __restrict__ lo) {
    const size_t i = ((size_t)blockIdx.x * 256 + threadIdx.x) * 4;
    split4(*(const float4*)(x + i), (__nv_bfloat162*)(hi + i), (__nv_bfloat162*)(lo + i));
}

__global__ void convert_split_pe(const float* __restrict__ x,
                                 const float* __restrict__ pe,
                                 __nv_bfloat16* __restrict__ hi,
                                 __nv_bfloat16* __restrict__ lo) {
    const size_t i = ((size_t)blockIdx.x * 256 + threadIdx.x) * 4;
    float4 v = *(const float4*)(x + i);
    const int d = (int)(i & (DDIM - 1));
    v.x += pe[d + 0]; v.y += pe[d + 1]; v.z += pe[d + 2]; v.w += pe[d + 3];
    split4(v, (__nv_bfloat162*)(hi + i), (__nv_bfloat162*)(lo + i));
}

// ---------------------------------------------------------------------------
// Per-position 8x8 head-mix attention (fp32)
// ---------------------------------------------------------------------------
__global__ void attn_kernel(const float* __restrict__ Q,
                            const float* __restrict__ K,
                            const float* __restrict__ V,
                            float* __restrict__ O) {
    __shared__ float sq[1024];
    __shared__ float sk[1024];
    __shared__ float sw[64];

    const int p = blockIdx.x;
    const int t = threadIdx.x;
    const size_t base = (size_t)p * 1024;

    ((float4*)sq)[t]       = ((const float4*)(Q + base))[t];
    ((float4*)sq)[t + 128] = ((const float4*)(Q + base))[t + 128];
    ((float4*)sk)[t]       = ((const float4*)(K + base))[t];
    ((float4*)sk)[t + 128] = ((const float4*)(K + base))[t + 128];
    __syncthreads();

    if (t < 64) {
        const int i = t >> 3, j = t & 7;
        const float* qi = &sq[i * 128];
        const float* kj = &sk[j * 128];
        float s = 0.0f;
#pragma unroll 8
        for (int h = 0; h < 128; h++) s += qi[h] * kj[h];
        sw[t] = s * 0.08838834764831845f;
    }
    __syncthreads();

    if (t < 8) {
        float m = sw[t * 8];
#pragma unroll
        for (int j = 1; j < 8; j++) m = fmaxf(m, sw[t * 8 + j]);
        float s = 0.0f;
        float e[8];
#pragma unroll
        for (int j = 0; j < 8; j++) { e[j] = __expf(sw[t * 8 + j] - m); s += e[j]; }
        const float inv = 1.0f / s;
#pragma unroll
        for (int j = 0; j < 8; j++) sw[t * 8 + j] = e[j] * inv;
    }
    __syncthreads();

    float vj[8];
#pragma unroll
    for (int j = 0; j < 8; j++) vj[j] = V[base + j * 128 + t];
#pragma unroll
    for (int i = 0; i < 8; i++) {
        float acc = 0.0f;
#pragma unroll
        for (int j = 0; j < 8; j++) acc += sw[i * 8 + j] * vj[j];
        O[base + i * 128 + t] = acc;
    }
}

// ---------------------------------------------------------------------------
// Launch
// ---------------------------------------------------------------------------
extern "C" void kernel_launch(void* const* d_in, const int* in_sizes, int n_in,
                              void* d_out, int out_size) {
    const float* input_seq  = (const float*)d_in[0];
    const float* output_seq = (const float*)d_in[1];
    const float* pe         = (const float*)d_in[2];
    const float* W[14] = {
        (const float*)d_in[3],  (const float*)d_in[5],  (const float*)d_in[7],
        (const float*)d_in[9],  (const float*)d_in[11],
        (const float*)d_in[13], (const float*)d_in[15], (const float*)d_in[17],
        (const float*)d_in[19], (const float*)d_in[21], (const float*)d_in[23],
        (const float*)d_in[25], (const float*)d_in[27], (const float*)d_in[29]
    };
    const float* Bv[14] = {
        (const float*)d_in[4],  (const float*)d_in[6],  (const float*)d_in[8],
        (const float*)d_in[10], (const float*)d_in[12],
        (const float*)d_in[14], (const float*)d_in[16], (const float*)d_in[18],
        (const float*)d_in[20], (const float*)d_in[22], (const float*)d_in[24],
        (const float*)d_in[26], (const float*)d_in[28], (const float*)d_in[30]
    };

    float* fbase = nullptr;
    cudaGetSymbolAddress((void**)&fbase, g_bufs);
    float* T0 = fbase + 0ull * MDIM * DDIM;
    float* T1 = fbase + 1ull * MDIM * DDIM;
    float* T2 = fbase + 2ull * MDIM * DDIM;
    float* T3 = fbase + 3ull * MDIM * DDIM;
    float* T4 = fbase + 4ull * MDIM * DDIM;
    float* T5 = fbase + 5ull * MDIM * DDIM;
    __nv_bfloat16 *Ahi, *Alo, *Whi, *Wlo;
    cudaGetSymbolAddress((void**)&Ahi, g_ahi);
    cudaGetSymbolAddress((void**)&Alo, g_alo);
    cudaGetSymbolAddress((void**)&Whi, g_whi);
    cudaGetSymbolAddress((void**)&Wlo, g_wlo);
    float* OUT = (float*)d_out;

    cudaFuncSetAttribute(gemm_bf16x3<false>, cudaFuncAttributeMaxDynamicSharedMemorySize, GEMM_SMEM);
    cudaFuncSetAttribute(gemm_bf16x3<true>,  cudaFuncAttributeMaxDynamicSharedMemorySize, GEMM_SMEM);

    const dim3 ggrid(DDIM / BN, MDIM / BM);      // (8, 128)
    const int CA_BLK = MDIM * DDIM / (4 * 256);  // activations
    const int CW_BLK = DDIM * DDIM / (4 * 256);  // weights

    auto gemm = [&](int wi, float* Cout, bool relu) {
        convert_split<<<CW_BLK, 256>>>(W[wi], Whi, Wlo);
        if (relu)
            gemm_bf16x3<true><<<ggrid, 256, GEMM_SMEM>>>(Ahi, Alo, Whi, Wlo, Bv[wi], Cout);
        else
            gemm_bf16x3<false><<<ggrid, 256, GEMM_SMEM>>>(Ahi, Alo, Whi, Wlo, Bv[wi], Cout);
    };

    // ---- encoder ----
    convert_split_pe<<<CA_BLK, 256>>>(input_seq, pe, Ahi, Alo);
    gemm(0, T1, false);
    gemm(1, T2, false);
    gemm(2, T3, false);
    attn_kernel<<<MDIM, 128>>>(T1, T2, T3, T4);
    convert_split<<<CA_BLK, 256>>>(T4, Ahi, Alo);
    gemm(3, T5, true);
    convert_split<<<CA_BLK, 256>>>(T5, Ahi, Alo);
    gemm(4, T0, false);   // enc_out -> T0

    // ---- decoder self-attn ----
    convert_split<<<CA_BLK, 256>>>(output_seq, Ahi, Alo);
    gemm(5, T1, false);
    gemm(6, T2, false);
    gemm(7, T3, false);
    attn_kernel<<<MDIM, 128>>>(T1, T2, T3, T4);   // sa -> T4

    // ---- decoder cross-attn ----
    convert_split<<<CA_BLK, 256>>>(T4, Ahi, Alo);
    gemm(8, T1, false);
    convert_split<<<CA_BLK, 256>>>(T0, Ahi, Alo);
    gemm(9, T2, false);
    gemm(10, T3, false);
    attn_kernel<<<MDIM, 128>>>(T1, T2, T3, T5);   // ca -> T5

    // ---- decoder FFN + fc ----
    convert_split<<<CA_BLK, 256>>>(T5, Ahi, Alo);
    gemm(11, T1, true);
    convert_split<<<CA_BLK, 256>>>(T1, Ahi, Alo);
    gemm(12, T2, false);
    convert_split<<<CA_BLK, 256>>>(T2, Ahi, Alo);
    gemm(13, OUT, false);
}

// round 4
// speedup vs baseline: 1.6504x; 1.0253x over previous
#include <cuda_runtime.h>
#include <cuda_bf16.h>
#include <cstdint>

// ---------------------------------------------------------------------------
// DialogueTransformer on GB300 (sm_103a, base sm_103 PTX target => mma.sync).
// bf16x3 split-precision HMMA GEMMs with fused split epilogues:
//  - GEMM outputs feeding GEMMs are written directly as bf16 hi/lo pairs.
//  - QKV (N=3072) and cross-KV (N=2048) batched into single launches.
//  - attention kernels emit hi/lo pairs directly.
// ---------------------------------------------------------------------------

#define MDIM 16384
#define DDIM 1024

// fp32 wide outputs for attention inputs
__device__ __align__(256) float g_qkv[MDIM * 3 * DDIM];   // 192 MB
__device__ __align__(256) float g_kv[MDIM * 2 * DDIM];    // 128 MB
// bf16 hi/lo activation pairs
__device__ __align__(256) __nv_bfloat16 g_p0h[MDIM * DDIM], g_p0l[MDIM * DDIM];
__device__ __align__(256) __nv_bfloat16 g_p1h[MDIM * DDIM], g_p1l[MDIM * DDIM];
__device__ __align__(256) __nv_bfloat16 g_p2h[MDIM * DDIM], g_p2l[MDIM * DDIM];
__device__ __align__(256) __nv_bfloat16 g_eh[MDIM * DDIM],  g_el[MDIM * DDIM];
// weight pairs (up to 3 concatenated)
__device__ __align__(256) __nv_bfloat16 g_whi[3 * DDIM * DDIM], g_wlo[3 * DDIM * DDIM];

// ---------------------------------------------------------------------------
// PTX helpers (baseline sm_80+ PTX only)
// ---------------------------------------------------------------------------
__device__ __forceinline__ uint32_t smem_to_u32(const void* p) {
    uint32_t a;
    asm("{ .reg .u64 t; cvta.to.shared.u64 t, %1; cvt.u32.u64 %0, t; }" : "=r"(a) : "l"(p));
    return a;
}
__device__ __forceinline__ void cp_async16(uint32_t saddr, const void* gptr) {
    asm volatile("cp.async.cg.shared.global [%0], [%1], 16;" :: "r"(saddr), "l"(gptr));
}
__device__ __forceinline__ void cp_commit() { asm volatile("cp.async.commit_group;"); }
__device__ __forceinline__ void cp_wait_all() { asm volatile("cp.async.wait_group 0;" ::: "memory"); }

__device__ __forceinline__ void ldsm_x4(uint32_t* r, uint32_t addr) {
    asm volatile("ldmatrix.sync.aligned.m8n8.x4.shared.b16 {%0,%1,%2,%3}, [%4];"
                 : "=r"(r[0]), "=r"(r[1]), "=r"(r[2]), "=r"(r[3]) : "r"(addr));
}
__device__ __forceinline__ void mma16816(float* c, const uint32_t* a,
                                         uint32_t b0, uint32_t b1) {
    asm volatile(
        "mma.sync.aligned.m16n8k16.row.col.f32.bf16.bf16.f32 "
        "{%0,%1,%2,%3}, {%4,%5,%6,%7}, {%8,%9}, {%0,%1,%2,%3};"
        : "+f"(c[0]), "+f"(c[1]), "+f"(c[2]), "+f"(c[3])
        : "r"(a[0]), "r"(a[1]), "r"(a[2]), "r"(a[3]), "r"(b0), "r"(b1));
}

// ---------------------------------------------------------------------------
// bf16x3 GEMM: out[m, gn] = sum_k A[m,k]*W[gn,k] + bias(gn)
// gn = blockIdx.x*128 + local. W is (possibly concatenated) [gridDim.x*128, 1024].
// bias selected per 1024-column group from b0/b1/b2.
// Output: fp32 C (ldc row stride) OR bf16 hi/lo pair (SPLIT, ldc=1024).
// BM=128, BN=128, BK=32, 256 threads, 8 warps (2x4 -> 64x32 warp tiles).
// ---------------------------------------------------------------------------
#define BM 128
#define BN 128
#define BK 32
#define NKB (DDIM / BK)   // 32
#define ROWB 80
#define TILE_BYTES (128 * ROWB)
#define STAGE_BYTES (4 * TILE_BYTES)
#define GEMM_SMEM (2 * STAGE_BYTES)   // 81920

template <bool RELU, bool SPLIT>
__global__ __launch_bounds__(256)
void gemm_bf16x3(const __nv_bfloat16* __restrict__ Ahi,
                 const __nv_bfloat16* __restrict__ Alo,
                 const __nv_bfloat16* __restrict__ Whi,
                 const __nv_bfloat16* __restrict__ Wlo,
                 const float* __restrict__ b0,
                 const float* __restrict__ b1,
                 const float* __restrict__ b2,
                 float* __restrict__ Cf,
                 __nv_bfloat16* __restrict__ Chi,
                 __nv_bfloat16* __restrict__ Clo,
                 int ldc) {
    extern __shared__ char smem[];
    const uint32_t sb = smem_to_u32(smem);
    const int tid = threadIdx.x;
    const int wid = tid >> 5;
    const int lane = tid & 31;
    const int bm = blockIdx.y * BM;
    const int gn = blockIdx.x * BN;       // global output column base
    const int wm = (wid & 1) * 64;
    const int wn = (wid >> 1) * 32;

    auto OFF_AH = [](int s) { return s * STAGE_BYTES + 0 * TILE_BYTES; };
    auto OFF_AL = [](int s) { return s * STAGE_BYTES + 1 * TILE_BYTES; };
    auto OFF_BH = [](int s) { return s * STAGE_BYTES + 2 * TILE_BYTES; };
    auto OFF_BL = [](int s) { return s * STAGE_BYTES + 3 * TILE_BYTES; };

    const int fr = tid >> 1;
    const int fc0 = (tid & 1) * 2;
    const __nv_bfloat16* gAh = Ahi + (size_t)(bm + fr) * DDIM;
    const __nv_bfloat16* gAl = Alo + (size_t)(bm + fr) * DDIM;
    const __nv_bfloat16* gBh = Whi + (size_t)(gn + fr) * DDIM;
    const __nv_bfloat16* gBl = Wlo + (size_t)(gn + fr) * DDIM;

    auto fill_stage = [&](int s, int kb) {
        const int k0 = kb * BK;
        const uint32_t srow = fr * ROWB;
#pragma unroll
        for (int i = 0; i < 2; i++) {
            const int c = fc0 + i;
            const uint32_t so = srow + c * 16;
            const int go = k0 + c * 8;
            cp_async16(sb + OFF_AH(s) + so, gAh + go);
            cp_async16(sb + OFF_AL(s) + so, gAl + go);
            cp_async16(sb + OFF_BH(s) + so, gBh + go);
            cp_async16(sb + OFF_BL(s) + so, gBl + go);
        }
        cp_commit();
    };

    fill_stage(0, 0);
    cp_wait_all();
    __syncthreads();

    float acc[4][4][4];
#pragma unroll
    for (int i = 0; i < 4; i++)
#pragma unroll
        for (int j = 0; j < 4; j++)
#pragma unroll
            for (int q = 0; q < 4; q++) acc[i][j][q] = 0.0f;

    const uint32_t lrow = (lane & 15);
    const uint32_t lcol = (lane >> 4) * 16;

    for (int kb = 0; kb < NKB; kb++) {
        const int s = kb & 1;
        if (kb + 1 < NKB) fill_stage(s ^ 1, kb + 1);

        const uint32_t aHb = sb + OFF_AH(s) + (wm + lrow) * ROWB + lcol;
        const uint32_t aLb = sb + OFF_AL(s) + (wm + lrow) * ROWB + lcol;
        const uint32_t bHb = sb + OFF_BH(s) + (wn + lrow) * ROWB + lcol;
        const uint32_t bLb = sb + OFF_BL(s) + (wn + lrow) * ROWB + lcol;

#pragma unroll
        for (int ks = 0; ks < 2; ks++) {
            const uint32_t ko = ks * 32;
            uint32_t ah[4][4], al[4][4], bh[2][4], bl[2][4];
#pragma unroll
            for (int p = 0; p < 2; p++) {
                ldsm_x4(bh[p], bHb + p * (16 * ROWB) + ko);
                ldsm_x4(bl[p], bLb + p * (16 * ROWB) + ko);
            }
#pragma unroll
            for (int mt = 0; mt < 4; mt++) {
                ldsm_x4(ah[mt], aHb + mt * (16 * ROWB) + ko);
                ldsm_x4(al[mt], aLb + mt * (16 * ROWB) + ko);
            }
#pragma unroll
            for (int mt = 0; mt < 4; mt++) {
#pragma unroll
                for (int nt = 0; nt < 4; nt++) {
                    const int p = nt >> 1, o = nt & 1;
                    mma16816(acc[mt][nt], ah[mt], bh[p][o], bh[p][o + 2]);
                    mma16816(acc[mt][nt], ah[mt], bl[p][o], bl[p][o + 2]);
                    mma16816(acc[mt][nt], al[mt], bh[p][o], bh[p][o + 2]);
                }
            }
        }
        if (kb + 1 < NKB) cp_wait_all();
        __syncthreads();
    }

    // ---- epilogue ----
    const int g = lane >> 2, t4 = lane & 3;
    const float* bias = (blockIdx.x < 8) ? b0 : ((blockIdx.x < 16) ? b1 : b2);
    const int bb = (blockIdx.x & 7) * BN + wn;   // bias offset within its 1024 group

#pragma unroll
    for (int mt = 0; mt < 4; mt++) {
        const int row0 = bm + wm + mt * 16 + g;
#pragma unroll
        for (int nt = 0; nt < 4; nt++) {
            const int col = nt * 8 + 2 * t4;
            const float bx = bias[bb + col];
            const float by = bias[bb + col + 1];
            float2 v0, v1;
            v0.x = acc[mt][nt][0] + bx;
            v0.y = acc[mt][nt][1] + by;
            v1.x = acc[mt][nt][2] + bx;
            v1.y = acc[mt][nt][3] + by;
            if (RELU) {
                v0.x = fmaxf(v0.x, 0.0f); v0.y = fmaxf(v0.y, 0.0f);
                v1.x = fmaxf(v1.x, 0.0f); v1.y = fmaxf(v1.y, 0.0f);
            }
            if (SPLIT) {
                const size_t o0 = (size_t)row0 * DDIM + gn + wn + col;
                const size_t o1 = o0 + 8 * DDIM;
                __nv_bfloat16 h0 = __float2bfloat16_rn(v0.x);
                __nv_bfloat16 h1 = __float2bfloat16_rn(v0.y);
                __nv_bfloat16 h2 = __float2bfloat16_rn(v1.x);
                __nv_bfloat16 h3 = __float2bfloat16_rn(v1.y);
                *(__nv_bfloat162*)(Chi + o0) = __nv_bfloat162(h0, h1);
                *(__nv_bfloat162*)(Chi + o1) = __nv_bfloat162(h2, h3);
                *(__nv_bfloat162*)(Clo + o0) = __nv_bfloat162(
                    __float2bfloat16_rn(v0.x - __bfloat162float(h0)),
                    __float2bfloat16_rn(v0.y - __bfloat162float(h1)));
                *(__nv_bfloat162*)(Clo + o1) = __nv_bfloat162(
                    __float2bfloat16_rn(v1.x - __bfloat162float(h2)),
                    __float2bfloat16_rn(v1.y - __bfloat162float(h3)));
            } else {
                const size_t o0 = (size_t)row0 * ldc + gn + wn + col;
                *(float2*)(Cf + o0) = v0;
                *(float2*)(Cf + o0 + 8 * (size_t)ldc) = v1;
            }
        }
    }
}

// ---------------------------------------------------------------------------
// fp32 -> (bf16 hi, bf16 lo) converters
// ---------------------------------------------------------------------------
__device__ __forceinline__ void split4(float4 v, __nv_bfloat162* H, __nv_bfloat162* L) {
    __nv_bfloat16 h0 = __float2bfloat16_rn(v.x);
    __nv_bfloat16 h1 = __float2bfloat16_rn(v.y);
    __nv_bfloat16 h2 = __float2bfloat16_rn(v.z);
    __nv_bfloat16 h3 = __float2bfloat16_rn(v.w);
    H[0] = __nv_bfloat162(h0, h1);
    H[1] = __nv_bfloat162(h2, h3);
    L[0] = __nv_bfloat162(__float2bfloat16_rn(v.x - __bfloat162float(h0)),
                          __float2bfloat16_rn(v.y - __bfloat162float(h1)));
    L[1] = __nv_bfloat162(__float2bfloat16_rn(v.z - __bfloat162float(h2)),
                          __float2bfloat16_rn(v.w - __bfloat162float(h3)));
}

__global__ void convert_split(const float* __restrict__ x,
                              __nv_bfloat16* __restrict__ hi,
                              __nv_bfloat16* __restrict__ lo) {
    const size_t i = ((size_t)blockIdx.x * 256 + threadIdx.x) * 4;
    split4(*(const float4*)(x + i), (__nv_bfloat162*)(hi + i), (__nv_bfloat162*)(lo + i));
}

__global__ void convert_split_pe(const float* __restrict__ x,
                                 const float* __restrict__ pe,
                                 __nv_bfloat16* __restrict__ hi,
                                 __nv_bfloat16* __restrict__ lo) {
    const size_t i = ((size_t)blockIdx.x * 256 + threadIdx.x) * 4;
    float4 v = *(const float4*)(x + i);
    const int d = (int)(i & (DDIM - 1));
    v.x += pe[d + 0]; v.y += pe[d + 1]; v.z += pe[d + 2]; v.w += pe[d + 3];
    split4(v, (__nv_bfloat162*)(hi + i), (__nv_bfloat162*)(lo + i));
}

// weight convert: up to 3 sources concatenated into hi/lo, 1M elements each
__global__ void convert_w(const float* __restrict__ w0,
                          const float* __restrict__ w1,
                          const float* __restrict__ w2,
                          __nv_bfloat16* __restrict__ hi,
                          __nv_bfloat16* __restrict__ lo) {
    const size_t i = ((size_t)blockIdx.x * 256 + threadIdx.x) * 4;
    const int which = (int)(i >> 20);
    const float* src = (which == 0) ? w0 : ((which == 1) ? w1 : w2);
    float4 v = *(const float4*)(src + (i & ((1u << 20) - 1)));
    split4(v, (__nv_bfloat162*)(hi + i), (__nv_bfloat162*)(lo + i));
}

// ---------------------------------------------------------------------------
// Per-position 8x8 head-mix attention; strided fp32 inputs, split pair output.
// ---------------------------------------------------------------------------
__global__ void attn_kernel(const float* __restrict__ Q, int qs,
                            const float* __restrict__ K, int ks_,
                            const float* __restrict__ V, int vs,
                            __nv_bfloat16* __restrict__ Ohi,
                            __nv_bfloat16* __restrict__ Olo) {
    __shared__ float sq[1024];
    __shared__ float sk[1024];
    __shared__ float sw[64];

    const int p = blockIdx.x;
    const int t = threadIdx.x;
    const float* Qb = Q + (size_t)p * qs;
    const float* Kb = K + (size_t)p * ks_;
    const float* Vb = V + (size_t)p * vs;

    ((float4*)sq)[t]       = ((const float4*)Qb)[t];
    ((float4*)sq)[t + 128] = ((const float4*)Qb)[t + 128];
    ((float4*)sk)[t]       = ((const float4*)Kb)[t];
    ((float4*)sk)[t + 128] = ((const float4*)Kb)[t + 128];
    __syncthreads();

    if (t < 64) {
        const int i = t >> 3, j = t & 7;
        const float* qi = &sq[i * 128];
        const float* kj = &sk[j * 128];
        float s = 0.0f;
#pragma unroll 8
        for (int h = 0; h < 128; h++) s += qi[h] * kj[h];
        sw[t] = s * 0.08838834764831845f;
    }
    __syncthreads();

    if (t < 8) {
        float m = sw[t * 8];
#pragma unroll
        for (int j = 1; j < 8; j++) m = fmaxf(m, sw[t * 8 + j]);
        float s = 0.0f;
        float e[8];
#pragma unroll
        for (int j = 0; j < 8; j++) { e[j] = __expf(sw[t * 8 + j] - m); s += e[j]; }
        const float inv = 1.0f / s;
#pragma unroll
        for (int j = 0; j < 8; j++) sw[t * 8 + j] = e[j] * inv;
    }
    __syncthreads();

    float vj[8];
#pragma unroll
    for (int j = 0; j < 8; j++) vj[j] = Vb[j * 128 + t];
    const size_t obase = (size_t)p * 1024;
#pragma unroll
    for (int i = 0; i < 8; i++) {
        float o = 0.0f;
#pragma unroll
        for (int j = 0; j < 8; j++) o += sw[i * 8 + j] * vj[j];
        __nv_bfloat16 h = __float2bfloat16_rn(o);
        Ohi[obase + i * 128 + t] = h;
        Olo[obase + i * 128 + t] = __float2bfloat16_rn(o - __bfloat162float(h));
    }
}

// ---------------------------------------------------------------------------
// Launch
// ---------------------------------------------------------------------------
extern "C" void kernel_launch(void* const* d_in, const int* in_sizes, int n_in,
                              void* d_out, int out_size) {
    const float* input_seq  = (const float*)d_in[0];
    const float* output_seq = (const float*)d_in[1];
    const float* pe         = (const float*)d_in[2];
    const float* enc_wq = (const float*)d_in[3];   const float* enc_bq = (const float*)d_in[4];
    const float* enc_wk = (const float*)d_in[5];   const float* enc_bk = (const float*)d_in[6];
    const float* enc_wv = (const float*)d_in[7];   const float* enc_bv = (const float*)d_in[8];
    const float* enc_w1 = (const float*)d_in[9];   const float* enc_b1 = (const float*)d_in[10];
    const float* enc_w2 = (const float*)d_in[11];  const float* enc_b2 = (const float*)d_in[12];
    const float* dec_s_wq = (const float*)d_in[13]; const float* dec_s_bq = (const float*)d_in[14];
    const float* dec_s_wk = (const float*)d_in[15]; const float* dec_s_bk = (const float*)d_in[16];
    const float* dec_s_wv = (const float*)d_in[17]; const float* dec_s_bv = (const float*)d_in[18];
    const float* dec_c_wq = (const float*)d_in[19]; const float* dec_c_bq = (const float*)d_in[20];
    const float* dec_c_wk = (const float*)d_in[21]; const float* dec_c_bk = (const float*)d_in[22];
    const float* dec_c_wv = (const float*)d_in[23]; const float* dec_c_bv = (const float*)d_in[24];
    const float* dec_w1 = (const float*)d_in[25];  const float* dec_b1 = (const float*)d_in[26];
    const float* dec_w2 = (const float*)d_in[27];  const float* dec_b2 = (const float*)d_in[28];
    const float* fc_w   = (const float*)d_in[29];  const float* fc_b   = (const float*)d_in[30];

    float *QKV, *KV;
    __nv_bfloat16 *P0h, *P0l, *P1h, *P1l, *P2h, *P2l, *Eh, *El, *Whi, *Wlo;
    cudaGetSymbolAddress((void**)&QKV, g_qkv);
    cudaGetSymbolAddress((void**)&KV, g_kv);
    cudaGetSymbolAddress((void**)&P0h, g_p0h);  cudaGetSymbolAddress((void**)&P0l, g_p0l);
    cudaGetSymbolAddress((void**)&P1h, g_p1h);  cudaGetSymbolAddress((void**)&P1l, g_p1l);
    cudaGetSymbolAddress((void**)&P2h, g_p2h);  cudaGetSymbolAddress((void**)&P2l, g_p2l);
    cudaGetSymbolAddress((void**)&Eh, g_eh);    cudaGetSymbolAddress((void**)&El, g_el);
    cudaGetSymbolAddress((void**)&Whi, g_whi);  cudaGetSymbolAddress((void**)&Wlo, g_wlo);
    float* OUT = (float*)d_out;

    cudaFuncSetAttribute(gemm_bf16x3<false,false>, cudaFuncAttributeMaxDynamicSharedMemorySize, GEMM_SMEM);
    cudaFuncSetAttribute(gemm_bf16x3<false,true>,  cudaFuncAttributeMaxDynamicSharedMemorySize, GEMM_SMEM);
    cudaFuncSetAttribute(gemm_bf16x3<true,true>,   cudaFuncAttributeMaxDynamicSharedMemorySize, GEMM_SMEM);

    const int CA_BLK = MDIM * DDIM / (4 * 256);
    const int CW1 = DDIM * DDIM / (4 * 256);          // 1024 blocks per weight

    // fp32 output GEMM (QKV / KV / fc)
    auto gemmF = [&](int ng, const __nv_bfloat16* Ah, const __nv_bfloat16* Al,
                     const float* b0, const float* b1, const float* b2,
                     float* C, int ldc) {
        gemm_bf16x3<false,false><<<dim3(ng * 8, MDIM / BM), 256, GEMM_SMEM>>>(
            Ah, Al, Whi, Wlo, b0, b1, b2, C, nullptr, nullptr, ldc);
    };
    // split output GEMM (ffn chains)
    auto gemmS = [&](const __nv_bfloat16* Ah, const __nv_bfloat16* Al,
                     const float* b0, __nv_bfloat16* Ch, __nv_bfloat16* Cl, bool relu) {
        if (relu)
            gemm_bf16x3<true,true><<<dim3(8, MDIM / BM), 256, GEMM_SMEM>>>(
                Ah, Al, Whi, Wlo, b0, b0, b0, nullptr, Ch, Cl, DDIM);
        else
            gemm_bf16x3<false,true><<<dim3(8, MDIM / BM), 256, GEMM_SMEM>>>(
                Ah, Al, Whi, Wlo, b0, b0, b0, nullptr, Ch, Cl, DDIM);
    };

    // ---- encoder ----
    convert_split_pe<<<CA_BLK, 256>>>(input_seq, pe, P0h, P0l);
    convert_w<<<3 * CW1, 256>>>(enc_wq, enc_wk, enc_wv, Whi, Wlo);
    gemmF(3, P0h, P0l, enc_bq, enc_bk, enc_bv, QKV, 3 * DDIM);
    attn_kernel<<<MDIM, 128>>>(QKV, 3 * DDIM, QKV + DDIM, 3 * DDIM, QKV + 2 * DDIM, 3 * DDIM, P1h, P1l);
    convert_w<<<CW1, 256>>>(enc_w1, enc_w1, enc_w1, Whi, Wlo);
    gemmS(P1h, P1l, enc_b1, P2h, P2l, true);
    convert_w<<<CW1, 256>>>(enc_w2, enc_w2, enc_w2, Whi, Wlo);
    gemmS(P2h, P2l, enc_b2, Eh, El, false);          // enc_out pair

    // ---- decoder self-attn ----
    convert_split<<<CA_BLK, 256>>>(output_seq, P0h, P0l);
    convert_w<<<3 * CW1, 256>>>(dec_s_wq, dec_s_wk, dec_s_wv, Whi, Wlo);
    gemmF(3, P0h, P0l, dec_s_bq, dec_s_bk, dec_s_bv, QKV, 3 * DDIM);
    attn_kernel<<<MDIM, 128>>>(QKV, 3 * DDIM, QKV + DDIM, 3 * DDIM, QKV + 2 * DDIM, 3 * DDIM, P1h, P1l);

    // ---- decoder cross-attn ----
    convert_w<<<CW1, 256>>>(dec_c_wq, dec_c_wq, dec_c_wq, Whi, Wlo);
    gemmF(1, P1h, P1l, dec_c_bq, dec_c_bq, dec_c_bq, QKV, DDIM);         // Q
    convert_w<<<2 * CW1, 256>>>(dec_c_wk, dec_c_wv, dec_c_wv, Whi, Wlo);
    gemmF(2, Eh, El, dec_c_bk, dec_c_bv, dec_c_bv, KV, 2 * DDIM);        // K,V
    attn_kernel<<<MDIM, 128>>>(QKV, DDIM, KV, 2 * DDIM, KV + DDIM, 2 * DDIM, P2h, P2l);

    // ---- decoder FFN + fc ----
    convert_w<<<CW1, 256>>>(dec_w1, dec_w1, dec_w1, Whi, Wlo);
    gemmS(P2h, P2l, dec_b1, P1h, P1l, true);
    convert_w<<<CW1, 256>>>(dec_w2, dec_w2, dec_w2, Whi, Wlo);
    gemmS(P1h, P1l, dec_b2, P0h, P0l, false);
    convert_w<<<CW1, 256>>>(fc_w, fc_w, fc_w, Whi, Wlo);
    gemmF(1, P0h, P0l, fc_b, fc_b, fc_b, OUT, DDIM);
}

// round 5
// speedup vs baseline: 1.7639x; 1.0687x over previous
#include <cuda_runtime.h>
#include <cuda_bf16.h>
#include <cstdint>

// ---------------------------------------------------------------------------
// DialogueTransformer on GB300 (sm_103a, base sm_103 PTX => mma.sync HMMA).
// bf16x3 split-precision GEMMs, fused split epilogues, batched QKV/KV.
// R5: GEMM 2 CTAs/SM (launch_bounds(256,2), reduced reg pressure);
//     attn smem padded to 132 floats/row + float4 score loop.
// ---------------------------------------------------------------------------

#define MDIM 16384
#define DDIM 1024

__device__ __align__(256) float g_qkv[MDIM * 3 * DDIM];
__device__ __align__(256) float g_kv[MDIM * 2 * DDIM];
__device__ __align__(256) __nv_bfloat16 g_p0h[MDIM * DDIM], g_p0l[MDIM * DDIM];
__device__ __align__(256) __nv_bfloat16 g_p1h[MDIM * DDIM], g_p1l[MDIM * DDIM];
__device__ __align__(256) __nv_bfloat16 g_p2h[MDIM * DDIM], g_p2l[MDIM * DDIM];
__device__ __align__(256) __nv_bfloat16 g_eh[MDIM * DDIM],  g_el[MDIM * DDIM];
__device__ __align__(256) __nv_bfloat16 g_whi[3 * DDIM * DDIM], g_wlo[3 * DDIM * DDIM];

// ---------------------------------------------------------------------------
// PTX helpers (baseline sm_80+ PTX only)
// ---------------------------------------------------------------------------
__device__ __forceinline__ uint32_t smem_to_u32(const void* p) {
    uint32_t a;
    asm("{ .reg .u64 t; cvta.to.shared.u64 t, %1; cvt.u32.u64 %0, t; }" : "=r"(a) : "l"(p));
    return a;
}
__device__ __forceinline__ void cp_async16(uint32_t saddr, const void* gptr) {
    asm volatile("cp.async.cg.shared.global [%0], [%1], 16;" :: "r"(saddr), "l"(gptr));
}
__device__ __forceinline__ void cp_commit() { asm volatile("cp.async.commit_group;"); }
__device__ __forceinline__ void cp_wait_all() { asm volatile("cp.async.wait_group 0;" ::: "memory"); }

__device__ __forceinline__ void ldsm_x4(uint32_t* r, uint32_t addr) {
    asm volatile("ldmatrix.sync.aligned.m8n8.x4.shared.b16 {%0,%1,%2,%3}, [%4];"
                 : "=r"(r[0]), "=r"(r[1]), "=r"(r[2]), "=r"(r[3]) : "r"(addr));
}
__device__ __forceinline__ void mma16816(float* c, const uint32_t* a,
                                         uint32_t b0, uint32_t b1) {
    asm volatile(
        "mma.sync.aligned.m16n8k16.row.col.f32.bf16.bf16.f32 "
        "{%0,%1,%2,%3}, {%4,%5,%6,%7}, {%8,%9}, {%0,%1,%2,%3};"
        : "+f"(c[0]), "+f"(c[1]), "+f"(c[2]), "+f"(c[3])
        : "r"(a[0]), "r"(a[1]), "r"(a[2]), "r"(a[3]), "r"(b0), "r"(b1));
}

// ---------------------------------------------------------------------------
// bf16x3 GEMM. BM=128, BN=128, BK=32, 256 thr, 8 warps (2x4 -> 64x32 tiles).
// ---------------------------------------------------------------------------
#define BM 128
#define BN 128
#define BK 32
#define NKB (DDIM / BK)
#define ROWB 80
#define TILE_BYTES (128 * ROWB)
#define STAGE_BYTES (4 * TILE_BYTES)
#define GEMM_SMEM (2 * STAGE_BYTES)   // 81920 -> 2 CTAs/SM (160KB < 228KB)

template <bool RELU, bool SPLIT>
__global__ __launch_bounds__(256, 2)
void gemm_bf16x3(const __nv_bfloat16* __restrict__ Ahi,
                 const __nv_bfloat16* __restrict__ Alo,
                 const __nv_bfloat16* __restrict__ Whi,
                 const __nv_bfloat16* __restrict__ Wlo,
                 const float* __restrict__ b0,
                 const float* __restrict__ b1,
                 const float* __restrict__ b2,
                 float* __restrict__ Cf,
                 __nv_bfloat16* __restrict__ Chi,
                 __nv_bfloat16* __restrict__ Clo,
                 int ldc) {
    extern __shared__ char smem[];
    const uint32_t sb = smem_to_u32(smem);
    const int tid = threadIdx.x;
    const int wid = tid >> 5;
    const int lane = tid & 31;
    const int bm = blockIdx.y * BM;
    const int gn = blockIdx.x * BN;
    const int wm = (wid & 1) * 64;
    const int wn = (wid >> 1) * 32;

    auto OFF_AH = [](int s) { return s * STAGE_BYTES + 0 * TILE_BYTES; };
    auto OFF_AL = [](int s) { return s * STAGE_BYTES + 1 * TILE_BYTES; };
    auto OFF_BH = [](int s) { return s * STAGE_BYTES + 2 * TILE_BYTES; };
    auto OFF_BL = [](int s) { return s * STAGE_BYTES + 3 * TILE_BYTES; };

    const int fr = tid >> 1;
    const int fc0 = (tid & 1) * 2;
    const __nv_bfloat16* gAh = Ahi + (size_t)(bm + fr) * DDIM;
    const __nv_bfloat16* gAl = Alo + (size_t)(bm + fr) * DDIM;
    const __nv_bfloat16* gBh = Whi + (size_t)(gn + fr) * DDIM;
    const __nv_bfloat16* gBl = Wlo + (size_t)(gn + fr) * DDIM;

    auto fill_stage = [&](int s, int kb) {
        const int k0 = kb * BK;
        const uint32_t srow = fr * ROWB;
#pragma unroll
        for (int i = 0; i < 2; i++) {
            const int c = fc0 + i;
            const uint32_t so = srow + c * 16;
            const int go = k0 + c * 8;
            cp_async16(sb + OFF_AH(s) + so, gAh + go);
            cp_async16(sb + OFF_AL(s) + so, gAl + go);
            cp_async16(sb + OFF_BH(s) + so, gBh + go);
            cp_async16(sb + OFF_BL(s) + so, gBl + go);
        }
        cp_commit();
    };

    fill_stage(0, 0);
    cp_wait_all();
    __syncthreads();

    float acc[4][4][4];
#pragma unroll
    for (int i = 0; i < 4; i++)
#pragma unroll
        for (int j = 0; j < 4; j++)
#pragma unroll
            for (int q = 0; q < 4; q++) acc[i][j][q] = 0.0f;

    const uint32_t lrow = (lane & 15);
    const uint32_t lcol = (lane >> 4) * 16;

    for (int kb = 0; kb < NKB; kb++) {
        const int s = kb & 1;
        if (kb + 1 < NKB) fill_stage(s ^ 1, kb + 1);

        const uint32_t aHb = sb + OFF_AH(s) + (wm + lrow) * ROWB + lcol;
        const uint32_t aLb = sb + OFF_AL(s) + (wm + lrow) * ROWB + lcol;
        const uint32_t bHb = sb + OFF_BH(s) + (wn + lrow) * ROWB + lcol;
        const uint32_t bLb = sb + OFF_BL(s) + (wn + lrow) * ROWB + lcol;

#pragma unroll
        for (int ks = 0; ks < 2; ks++) {
            const uint32_t ko = ks * 32;
            uint32_t bh[2][4], bl[2][4];
#pragma unroll
            for (int p = 0; p < 2; p++) {
                ldsm_x4(bh[p], bHb + p * (16 * ROWB) + ko);
                ldsm_x4(bl[p], bLb + p * (16 * ROWB) + ko);
            }
#pragma unroll
            for (int mt = 0; mt < 4; mt++) {
                uint32_t ah[4], al[4];
                ldsm_x4(ah, aHb + mt * (16 * ROWB) + ko);
                ldsm_x4(al, aLb + mt * (16 * ROWB) + ko);
#pragma unroll
                for (int nt = 0; nt < 4; nt++) {
                    const int p = nt >> 1, o = nt & 1;
                    mma16816(acc[mt][nt], ah, bh[p][o], bh[p][o + 2]);
                    mma16816(acc[mt][nt], ah, bl[p][o], bl[p][o + 2]);
                    mma16816(acc[mt][nt], al, bh[p][o], bh[p][o + 2]);
                }
            }
        }
        if (kb + 1 < NKB) cp_wait_all();
        __syncthreads();
    }

    // ---- epilogue ----
    const int g = lane >> 2, t4 = lane & 3;
    const float* bias = (blockIdx.x < 8) ? b0 : ((blockIdx.x < 16) ? b1 : b2);
    const int bb = (blockIdx.x & 7) * BN + wn;

#pragma unroll
    for (int mt = 0; mt < 4; mt++) {
        const int row0 = bm + wm + mt * 16 + g;
#pragma unroll
        for (int nt = 0; nt < 4; nt++) {
            const int col = nt * 8 + 2 * t4;
            const float bx = bias[bb + col];
            const float by = bias[bb + col + 1];
            float2 v0, v1;
            v0.x = acc[mt][nt][0] + bx;
            v0.y = acc[mt][nt][1] + by;
            v1.x = acc[mt][nt][2] + bx;
            v1.y = acc[mt][nt][3] + by;
            if (RELU) {
                v0.x = fmaxf(v0.x, 0.0f); v0.y = fmaxf(v0.y, 0.0f);
                v1.x = fmaxf(v1.x, 0.0f); v1.y = fmaxf(v1.y, 0.0f);
            }
            if (SPLIT) {
                const size_t o0 = (size_t)row0 * DDIM + gn + wn + col;
                const size_t o1 = o0 + 8 * DDIM;
                __nv_bfloat16 h0 = __float2bfloat16_rn(v0.x);
                __nv_bfloat16 h1 = __float2bfloat16_rn(v0.y);
                __nv_bfloat16 h2 = __float2bfloat16_rn(v1.x);
                __nv_bfloat16 h3 = __float2bfloat16_rn(v1.y);
                *(__nv_bfloat162*)(Chi + o0) = __nv_bfloat162(h0, h1);
                *(__nv_bfloat162*)(Chi + o1) = __nv_bfloat162(h2, h3);
                *(__nv_bfloat162*)(Clo + o0) = __nv_bfloat162(
                    __float2bfloat16_rn(v0.x - __bfloat162float(h0)),
                    __float2bfloat16_rn(v0.y - __bfloat162float(h1)));
                *(__nv_bfloat162*)(Clo + o1) = __nv_bfloat162(
                    __float2bfloat16_rn(v1.x - __bfloat162float(h2)),
                    __float2bfloat16_rn(v1.y - __bfloat162float(h3)));
            } else {
                const size_t o0 = (size_t)row0 * ldc + gn + wn + col;
                *(float2*)(Cf + o0) = v0;
                *(float2*)(Cf + o0 + 8 * (size_t)ldc) = v1;
            }
        }
    }
}

// ---------------------------------------------------------------------------
// fp32 -> (bf16 hi, bf16 lo) converters
// ---------------------------------------------------------------------------
__device__ __forceinline__ void split4(float4 v, __nv_bfloat162* H, __nv_bfloat162* L) {
    __nv_bfloat16 h0 = __float2bfloat16_rn(v.x);
    __nv_bfloat16 h1 = __float2bfloat16_rn(v.y);
    __nv_bfloat16 h2 = __float2bfloat16_rn(v.z);
    __nv_bfloat16 h3 = __float2bfloat16_rn(v.w);
    H[0] = __nv_bfloat162(h0, h1);
    H[1] = __nv_bfloat162(h2, h3);
    L[0] = __nv_bfloat162(__float2bfloat16_rn(v.x - __bfloat162float(h0)),
                          __float2bfloat16_rn(v.y - __bfloat162float(h1)));
    L[1] = __nv_bfloat162(__float2bfloat16_rn(v.z - __bfloat162float(h2)),
                          __float2bfloat16_rn(v.w - __bfloat162float(h3)));
}

__global__ void convert_split(const float* __restrict__ x,
                              __nv_bfloat16* __restrict__ hi,
                              __nv_bfloat16* __restrict__ lo) {
    const size_t i = ((size_t)blockIdx.x * 256 + threadIdx.x) * 4;
    split4(*(const float4*)(x + i), (__nv_bfloat162*)(hi + i), (__nv_bfloat162*)(lo + i));
}

__global__ void convert_split_pe(const float* __restrict__ x,
                                 const float* __restrict__ pe,
                                 __nv_bfloat16* __restrict__ hi,
                                 __nv_bfloat16* __restrict__ lo) {
    const size_t i = ((size_t)blockIdx.x * 256 + threadIdx.x) * 4;
    float4 v = *(const float4*)(x + i);
    const int d = (int)(i & (DDIM - 1));
    v.x += pe[d + 0]; v.y += pe[d + 1]; v.z += pe[d + 2]; v.w += pe[d + 3];
    split4(v, (__nv_bfloat162*)(hi + i), (__nv_bfloat162*)(lo + i));
}

__global__ void convert_w(const float* __restrict__ w0,
                          const float* __restrict__ w1,
                          const float* __restrict__ w2,
                          __nv_bfloat16* __restrict__ hi,
                          __nv_bfloat16* __restrict__ lo) {
    const size_t i = ((size_t)blockIdx.x * 256 + threadIdx.x) * 4;
    const int which = (int)(i >> 20);
    const float* src = (which == 0) ? w0 : ((which == 1) ? w1 : w2);
    float4 v = *(const float4*)(src + (i & ((1u << 20) - 1)));
    split4(v, (__nv_bfloat162*)(hi + i), (__nv_bfloat162*)(lo + i));
}

// ---------------------------------------------------------------------------
// Per-position 8x8 head-mix attention.
// Smem rows padded to 132 floats -> conflict-free; float4 score loop.
// ---------------------------------------------------------------------------
#define QROW 132

__global__ void attn_kernel(const float* __restrict__ Q, int qs,
                            const float* __restrict__ K, int ks_,
                            const float* __restrict__ V, int vs,
                            __nv_bfloat16* __restrict__ Ohi,
                            __nv_bfloat16* __restrict__ Olo) {
    __shared__ float sq[8 * QROW + 4];
    __shared__ float sk[8 * QROW + 4];
    __shared__ float sw[64];

    const int p = blockIdx.x;
    const int t = threadIdx.x;
    const float* Qb = Q + (size_t)p * qs;
    const float* Kb = K + (size_t)p * ks_;
    const float* Vb = V + (size_t)p * vs;

    // load 1024 floats each (2 float4 per thread), padded row stride
#pragma unroll
    for (int u = 0; u < 2; u++) {
        const int e = (t + u * 128) * 4;          // element index
        const int i = e >> 7, h = e & 127;
        *(float4*)(sq + i * QROW + h) = *(const float4*)(Qb + e);
        *(float4*)(sk + i * QROW + h) = *(const float4*)(Kb + e);
    }
    __syncthreads();

    if (t < 64) {
        const int i = t >> 3, j = t & 7;
        const float* qi = &sq[i * QROW];
        const float* kj = &sk[j * QROW];
        float s = 0.0f;
#pragma unroll
        for (int h = 0; h < 128; h += 4) {
            const float4 a = *(const float4*)(qi + h);
            const float4 b = *(const float4*)(kj + h);
            s += a.x * b.x + a.y * b.y + a.z * b.z + a.w * b.w;
        }
        sw[t] = s * 0.08838834764831845f;
    }
    __syncthreads();

    if (t < 8) {
        float m = sw[t * 8];
#pragma unroll
        for (int j = 1; j < 8; j++) m = fmaxf(m, sw[t * 8 + j]);
        float s = 0.0f;
        float e[8];
#pragma unroll
        for (int j = 0; j < 8; j++) { e[j] = __expf(sw[t * 8 + j] - m); s += e[j]; }
        const float inv = 1.0f / s;
#pragma unroll
        for (int j = 0; j < 8; j++) sw[t * 8 + j] = e[j] * inv;
    }
    __syncthreads();

    float vj[8];
#pragma unroll
    for (int j = 0; j < 8; j++) vj[j] = Vb[j * 128 + t];
    const size_t obase = (size_t)p * 1024;
#pragma unroll
    for (int i = 0; i < 8; i++) {
        float o = 0.0f;
#pragma unroll
        for (int j = 0; j < 8; j++) o += sw[i * 8 + j] * vj[j];
        __nv_bfloat16 h = __float2bfloat16_rn(o);
        Ohi[obase + i * 128 + t] = h;
        Olo[obase + i * 128 + t] = __float2bfloat16_rn(o - __bfloat162float(h));
    }
}

// ---------------------------------------------------------------------------
// Launch
// ---------------------------------------------------------------------------
extern "C" void kernel_launch(void* const* d_in, const int* in_sizes, int n_in,
                              void* d_out, int out_size) {
    const float* input_seq  = (const float*)d_in[0];
    const float* output_seq = (const float*)d_in[1];
    const float* pe         = (const float*)d_in[2];
    const float* enc_wq = (const float*)d_in[3];   const float* enc_bq = (const float*)d_in[4];
    const float* enc_wk = (const float*)d_in[5];   const float* enc_bk = (const float*)d_in[6];
    const float* enc_wv = (const float*)d_in[7];   const float* enc_bv = (const float*)d_in[8];
    const float* enc_w1 = (const float*)d_in[9];   const float* enc_b1 = (const float*)d_in[10];
    const float* enc_w2 = (const float*)d_in[11];  const float* enc_b2 = (const float*)d_in[12];
    const float* dec_s_wq = (const float*)d_in[13]; const float* dec_s_bq = (const float*)d_in[14];
    const float* dec_s_wk = (const float*)d_in[15]; const float* dec_s_bk = (const float*)d_in[16];
    const float* dec_s_wv = (const float*)d_in[17]; const float* dec_s_bv = (const float*)d_in[18];
    const float* dec_c_wq = (const float*)d_in[19]; const float* dec_c_bq = (const float*)d_in[20];
    const float* dec_c_wk = (const float*)d_in[21]; const float* dec_c_bk = (const float*)d_in[22];
    const float* dec_c_wv = (const float*)d_in[23]; const float* dec_c_bv = (const float*)d_in[24];
    const float* dec_w1 = (const float*)d_in[25];  const float* dec_b1 = (const float*)d_in[26];
    const float* dec_w2 = (const float*)d_in[27];  const float* dec_b2 = (const float*)d_in[28];
    const float* fc_w   = (const float*)d_in[29];  const float* fc_b   = (const float*)d_in[30];

    float *QKV, *KV;
    __nv_bfloat16 *P0h, *P0l, *P1h, *P1l, *P2h, *P2l, *Eh, *El, *Whi, *Wlo;
    cudaGetSymbolAddress((void**)&QKV, g_qkv);
    cudaGetSymbolAddress((void**)&KV, g_kv);
    cudaGetSymbolAddress((void**)&P0h, g_p0h);  cudaGetSymbolAddress((void**)&P0l, g_p0l);
    cudaGetSymbolAddress((void**)&P1h, g_p1h);  cudaGetSymbolAddress((void**)&P1l, g_p1l);
    cudaGetSymbolAddress((void**)&P2h, g_p2h);  cudaGetSymbolAddress((void**)&P2l, g_p2l);
    cudaGetSymbolAddress((void**)&Eh, g_eh);    cudaGetSymbolAddress((void**)&El, g_el);
    cudaGetSymbolAddress((void**)&Whi, g_whi);  cudaGetSymbolAddress((void**)&Wlo, g_wlo);
    float* OUT = (float*)d_out;

    cudaFuncSetAttribute(gemm_bf16x3<false,false>, cudaFuncAttributeMaxDynamicSharedMemorySize, GEMM_SMEM);
    cudaFuncSetAttribute(gemm_bf16x3<false,true>,  cudaFuncAttributeMaxDynamicSharedMemorySize, GEMM_SMEM);
    cudaFuncSetAttribute(gemm_bf16x3<true,true>,   cudaFuncAttributeMaxDynamicSharedMemorySize, GEMM_SMEM);

    const int CA_BLK = MDIM * DDIM / (4 * 256);
    const int CW1 = DDIM * DDIM / (4 * 256);

    auto gemmF = [&](int ng, const __nv_bfloat16* Ah, const __nv_bfloat16* Al,
                     const float* b0, const float* b1, const float* b2,
                     float* C, int ldc) {
        gemm_bf16x3<false,false><<<dim3(ng * 8, MDIM / BM), 256, GEMM_SMEM>>>(
            Ah, Al, Whi, Wlo, b0, b1, b2, C, nullptr, nullptr, ldc);
    };
    auto gemmS = [&](const __nv_bfloat16* Ah, const __nv_bfloat16* Al,
                     const float* b0, __nv_bfloat16* Ch, __nv_bfloat16* Cl, bool relu) {
        if (relu)
            gemm_bf16x3<true,true><<<dim3(8, MDIM / BM), 256, GEMM_SMEM>>>(
                Ah, Al, Whi, Wlo, b0, b0, b0, nullptr, Ch, Cl, DDIM);
        else
            gemm_bf16x3<false,true><<<dim3(8, MDIM / BM), 256, GEMM_SMEM>>>(
                Ah, Al, Whi, Wlo, b0, b0, b0, nullptr, Ch, Cl, DDIM);
    };

    // ---- encoder ----
    convert_split_pe<<<CA_BLK, 256>>>(input_seq, pe, P0h, P0l);
    convert_w<<<3 * CW1, 256>>>(enc_wq, enc_wk, enc_wv, Whi, Wlo);
    gemmF(3, P0h, P0l, enc_bq, enc_bk, enc_bv, QKV, 3 * DDIM);
    attn_kernel<<<MDIM, 128>>>(QKV, 3 * DDIM, QKV + DDIM, 3 * DDIM, QKV + 2 * DDIM, 3 * DDIM, P1h, P1l);
    convert_w<<<CW1, 256>>>(enc_w1, enc_w1, enc_w1, Whi, Wlo);
    gemmS(P1h, P1l, enc_b1, P2h, P2l, true);
    convert_w<<<CW1, 256>>>(enc_w2, enc_w2, enc_w2, Whi, Wlo);
    gemmS(P2h, P2l, enc_b2, Eh, El, false);

    // ---- decoder self-attn ----
    convert_split<<<CA_BLK, 256>>>(output_seq, P0h, P0l);
    convert_w<<<3 * CW1, 256>>>(dec_s_wq, dec_s_wk, dec_s_wv, Whi, Wlo);
    gemmF(3, P0h, P0l, dec_s_bq, dec_s_bk, dec_s_bv, QKV, 3 * DDIM);
    attn_kernel<<<MDIM, 128>>>(QKV, 3 * DDIM, QKV + DDIM, 3 * DDIM, QKV + 2 * DDIM, 3 * DDIM, P1h, P1l);

    // ---- decoder cross-attn ----
    convert_w<<<CW1, 256>>>(dec_c_wq, dec_c_wq, dec_c_wq, Whi, Wlo);
    gemmF(1, P1h, P1l, dec_c_bq, dec_c_bq, dec_c_bq, QKV, DDIM);
    convert_w<<<2 * CW1, 256>>>(dec_c_wk, dec_c_wv, dec_c_wv, Whi, Wlo);
    gemmF(2, Eh, El, dec_c_bk, dec_c_bv, dec_c_bv, KV, 2 * DDIM);
    attn_kernel<<<MDIM, 128>>>(QKV, DDIM, KV, 2 * DDIM, KV + DDIM, 2 * DDIM, P2h, P2l);

    // ---- decoder FFN + fc ----
    convert_w<<<CW1, 256>>>(dec_w1, dec_w1, dec_w1, Whi, Wlo);
    gemmS(P2h, P2l, dec_b1, P1h, P1l, true);
    convert_w<<<CW1, 256>>>(dec_w2, dec_w2, dec_w2, Whi, Wlo);
    gemmS(P1h, P1l, dec_b2, P0h, P0l, false);
    convert_w<<<CW1, 256>>>(fc_w, fc_w, fc_w, Whi, Wlo);
    gemmF(1, P0h, P0l, fc_b, fc_b, fc_b, OUT, DDIM);
}